// round 10
// baseline (speedup 1.0000x reference)
#include <cuda_runtime.h>
#include <cstdint>
#include <cstddef>

#define Bn 256
#define Ln 1024
#define Vn 40
#define Hn 128

// ---- packed f32x2 helpers (FFMA2 only reachable via PTX) ----
__device__ __forceinline__ unsigned long long ffma2(unsigned long long a,
                                                    unsigned long long b,
                                                    unsigned long long c) {
    unsigned long long d;
    asm("fma.rn.f32x2 %0, %1, %2, %3;" : "=l"(d) : "l"(a), "l"(b), "l"(c));
    return d;
}
__device__ __forceinline__ unsigned long long add2(unsigned long long a,
                                                   unsigned long long b) {
    unsigned long long d;
    asm("add.rn.f32x2 %0, %1, %2;" : "=l"(d) : "l"(a), "l"(b));
    return d;
}
__device__ __forceinline__ float plo(unsigned long long a) {
    return __int_as_float((int)(unsigned)(a & 0xffffffffull));
}
__device__ __forceinline__ float phi(unsigned long long a) {
    return __int_as_float((int)(unsigned)(a >> 32));
}
__device__ __forceinline__ float tanh_fast(float x) {
    float r;
    asm("tanh.approx.f32 %0, %1;" : "=f"(r) : "f"(x));
    return r;
}

// =====================================================================
// Fused CharRNN, full-row-per-thread version. One CTA per batch row,
// 128 threads. Thread t owns h element t and computes its FULL 128-k
// dot product (Wh row t entirely in registers, 64 u64). h is read via
// LDS.128 broadcast (all lanes same address). NO per-step partial
// exchange for h: tail = add2 -> extract -> +em(+bh prefolded) -> tanh
// -> STS.32 -> ONE barrier.
// Logits stay k-split (register budget): warps 0-1 accumulate logit
// row v=t (<40) over k[0,64); warps 2-3 row v=t-64 over k[64,128).
// Warp-uniform paths (equal FFMA2 per warp). Partials exchanged via
// double-buffered s_red written pre-BAR, read post-BAR.
// Logit timing: h loaded at iter l is the output of step l-1 -> the
// logit finalized after BAR of iter l is row l-1 (skip l=0); row Ln-1
// comes from an epilogue pass over the final h.
// =====================================================================
__global__ void __launch_bounds__(128, 2) fused_rnn_kernel(
    const int* __restrict__ x, const float* __restrict__ h0,
    const float* __restrict__ emb, const float* __restrict__ Wh,
    const float* __restrict__ Wo, const float* __restrict__ bh,
    const float* __restrict__ by, float* __restrict__ out,
    float* __restrict__ final_h)
{
    __shared__ __align__(16) float s_emb[Vn * Hn];   // 20 KB
    __shared__ int s_x[Ln];                          // 4 KB
    __shared__ __align__(16) float s_h[2][Hn];       // ping-pong h
    __shared__ float s_red[2][64];                   // logit partials, dbl-buf

    const int t   = threadIdx.x;
    const int b   = blockIdx.x;
    const int kh2 = t >> 6;            // 0: warps 0-1 (k lo-half), 1: warps 2-3
    const int vr  = t - (kh2 << 6);    // candidate logit row
    const bool dv = (vr < Vn);
    const float byv = dv ? by[vr] : 0.f;

    for (int i = t; i < Vn * Hn; i += 128) s_emb[i] = emb[i];
    for (int i = t; i < Ln; i += 128) s_x[i] = x[b * Ln + i];
    s_h[0][t] = h0[b * Hn + t];
    const float bh_t = bh[t];

    // Wh row t, full k: 64 u64 = 128 regs
    unsigned long long wh[64];
    {
        const ulonglong2* wp = (const ulonglong2*)(Wh + t * Hn);
#pragma unroll
        for (int i = 0; i < 32; i++) {
            ulonglong2 p = wp[i];
            wh[2 * i] = p.x; wh[2 * i + 1] = p.y;
        }
    }
    // Wo row vr, k-half kh2: 32 u64 = 64 regs (zeros if !dv)
    unsigned long long wo[32];
    if (dv) {
        const ulonglong2* wv = (const ulonglong2*)(Wo + vr * Hn + (kh2 << 6));
#pragma unroll
        for (int i = 0; i < 16; i++) {
            ulonglong2 p = wv[i];
            wo[2 * i] = p.x; wo[2 * i + 1] = p.y;
        }
    } else {
#pragma unroll
        for (int i = 0; i < 32; i++) wo[i] = 0ull;
    }
    __syncthreads();

    float* obase = out + (size_t)b * Ln * Vn;

    // em + bh prefolded, prefetched one step ahead
    float em_c = s_emb[s_x[0] * Hn + t] + bh_t;

#pragma unroll 1
    for (int l = 0; l < Ln; l++) {
        // h entering step l (== output of step l-1); LDS.128 broadcast
        const ulonglong2* hp = (const ulonglong2*)(s_h[l & 1]);

        unsigned long long a0 = 0, a1 = 0;   // h elem t (full k)
        unsigned long long g0 = 0, g1 = 0;   // logit row vr (my k-half)
        if (kh2 == 0) {                       // warp-uniform branch
#pragma unroll
            for (int i = 0; i < 16; i++) {    // k[0,64): h + logit
                ulonglong2 p = hp[i];
                a0 = ffma2(wh[2 * i],     p.x, a0);
                g0 = ffma2(wo[2 * i],     p.x, g0);
                a1 = ffma2(wh[2 * i + 1], p.y, a1);
                g1 = ffma2(wo[2 * i + 1], p.y, g1);
            }
#pragma unroll
            for (int i = 16; i < 32; i++) {   // k[64,128): h only
                ulonglong2 p = hp[i];
                a0 = ffma2(wh[2 * i],     p.x, a0);
                a1 = ffma2(wh[2 * i + 1], p.y, a1);
            }
        } else {
#pragma unroll
            for (int i = 0; i < 16; i++) {    // k[0,64): h only
                ulonglong2 p = hp[i];
                a0 = ffma2(wh[2 * i],     p.x, a0);
                a1 = ffma2(wh[2 * i + 1], p.y, a1);
            }
#pragma unroll
            for (int i = 16; i < 32; i++) {   // k[64,128): h + logit
                ulonglong2 p = hp[i];
                a0 = ffma2(wh[2 * i],          p.x, a0);
                g0 = ffma2(wo[2 * (i - 16)],   p.x, g0);
                a1 = ffma2(wh[2 * i + 1],      p.y, a1);
                g1 = ffma2(wo[2 * (i - 16) + 1], p.y, g1);
            }
        }
        a0 = add2(a0, a1);
        g0 = add2(g0, g1);
        const float hn = tanh_fast(plo(a0) + phi(a0) + em_c);
        const float lp = plo(g0) + phi(g0);

        s_h[(l + 1) & 1][t] = hn;             // coalesced STS.32
        if (kh2 == 0 && dv) s_red[l & 1][vr] = lp;

        // prefetch em+bh for step l+1 (hidden by BAR)
        em_c = s_emb[s_x[(l + 1) & (Ln - 1)] * Hn + t] + bh_t;

        __syncthreads();                      // single per-step barrier

        if (kh2 == 1 && dv && l > 0) {        // finalize logit row l-1
            obase[(size_t)(l - 1) * Vn + vr] =
                lp + s_red[l & 1][vr] + byv;
        }
    }

    // Epilogue: logit row Ln-1 from the final hidden state (s_h[0]).
    {
        const ulonglong2* hp = (const ulonglong2*)(s_h[0]) + (kh2 << 4);
        unsigned long long g0 = 0, g1 = 0;
#pragma unroll
        for (int i = 0; i < 16; i++) {
            ulonglong2 p = hp[i];
            g0 = ffma2(wo[2 * i],     p.x, g0);
            g1 = ffma2(wo[2 * i + 1], p.y, g1);
        }
        g0 = add2(g0, g1);
        const float lp = plo(g0) + phi(g0);
        if (kh2 == 0 && dv) s_red[0][vr] = lp;
        __syncthreads();
        if (kh2 == 1 && dv) {
            obase[(size_t)(Ln - 1) * Vn + vr] = lp + s_red[0][vr] + byv;
        }
    }

    final_h[b * Hn + t] = s_h[0][t];   // Ln even -> final state in buffer 0
}

extern "C" void kernel_launch(void* const* d_in, const int* in_sizes, int n_in,
                              void* d_out, int out_size)
{
    const int*   x   = (const int*)d_in[0];
    const float* h0  = (const float*)d_in[1];
    const float* emb = (const float*)d_in[2];
    const float* Wh  = (const float*)d_in[3];
    const float* Wo  = (const float*)d_in[4];
    const float* bh  = (const float*)d_in[5];
    const float* by  = (const float*)d_in[6];

    float* out     = (float*)d_out;
    float* logits  = out;                               // [B, L, V]
    float* final_h = out + (size_t)Bn * Ln * Vn;        // [B, H]

    fused_rnn_kernel<<<Bn, 128>>>(x, h0, emb, Wh, Wo, bh, by, logits, final_h);
}